// round 6
// baseline (speedup 1.0000x reference)
#include <cuda_runtime.h>
#include <cuda_bf16.h>
#include <cstdint>

// Sliding-window attention via mma.sync bf16 split (3xBF16 ~ fp32 precision).
// R6: cvt.rn.bf16x2-based splits (ALU cut), ex2 with folded log2e, per-warp
// edge-tile MMA skipping, single barrier per tile.
// B=1, H=16, S=8192, D=64, window read on device.

static constexpr int HH  = 16;
static constexpr int SEQ = 8192;
static constexpr int DD  = 64;
static constexpr int BQ  = 64;
static constexpr int BK  = 64;
static constexpr size_t KVN = (size_t)HH * SEQ * DD;   // 8388608

__device__ __nv_bfloat16 g_kh[KVN];
__device__ __nv_bfloat16 g_kl[KVN];
__device__ __nv_bfloat16 g_vh[KVN];
__device__ __nv_bfloat16 g_vl[KVN];

// ---------------- helpers ----------------
__device__ __forceinline__ uint32_t f2bf(float x) {      // rn bf16 bits
    uint32_t u = __float_as_uint(x);
    return (u + 0x7fffu + ((u >> 16) & 1u)) >> 16;
}
__device__ __forceinline__ float bf2f(uint32_t b) { return __uint_as_float(b << 16); }

// pack: upper = a, lower = b
__device__ __forceinline__ uint32_t cvt2(float a, float b) {
    uint32_t d;
    asm("cvt.rn.bf16x2.f32 %0, %1, %2;" : "=r"(d) : "f"(a), "f"(b));
    return d;
}
__device__ __forceinline__ float ex2f(float x) {
    float r;
    asm("ex2.approx.f32 %0, %1;" : "=f"(r) : "f"(x));
    return r;
}

__device__ __forceinline__ uint32_t smem_u32(const void* p) {
    uint32_t a;
    asm("{ .reg .u64 t; cvta.to.shared.u64 t, %1; cvt.u32.u64 %0, t; }" : "=r"(a) : "l"(p));
    return a;
}
#define SWZ(x) ((x) ^ (((x) >> 3) & 0x70))

__device__ __forceinline__ void cpasync16(uint32_t dst, const void* src, int sz) {
    asm volatile("cp.async.cg.shared.global [%0], [%1], 16, %2;"
                 :: "r"(dst), "l"(src), "r"(sz) : "memory");
}
#define CP_COMMIT() asm volatile("cp.async.commit_group;" ::: "memory")
#define CP_WAIT0()  asm volatile("cp.async.wait_group 0;" ::: "memory")

__device__ __forceinline__ void ldsm4(uint32_t& r0, uint32_t& r1, uint32_t& r2, uint32_t& r3,
                                      uint32_t addr) {
    asm volatile("ldmatrix.sync.aligned.m8n8.x4.shared.b16 {%0,%1,%2,%3}, [%4];"
                 : "=r"(r0), "=r"(r1), "=r"(r2), "=r"(r3) : "r"(addr));
}
__device__ __forceinline__ void ldsm4t(uint32_t& r0, uint32_t& r1, uint32_t& r2, uint32_t& r3,
                                       uint32_t addr) {
    asm volatile("ldmatrix.sync.aligned.m8n8.x4.trans.shared.b16 {%0,%1,%2,%3}, [%4];"
                 : "=r"(r0), "=r"(r1), "=r"(r2), "=r"(r3) : "r"(addr));
}
__device__ __forceinline__ void mma16816(float* c, const uint32_t* a, const uint32_t* b) {
    asm volatile("mma.sync.aligned.m16n8k16.row.col.f32.bf16.bf16.f32 "
                 "{%0,%1,%2,%3}, {%4,%5,%6,%7}, {%8,%9}, {%0,%1,%2,%3};"
                 : "+f"(c[0]), "+f"(c[1]), "+f"(c[2]), "+f"(c[3])
                 : "r"(a[0]), "r"(a[1]), "r"(a[2]), "r"(a[3]), "r"(b[0]), "r"(b[1]));
}

// ---------------- prepass: fp32 K,V -> bf16 hi/lo ----------------
__global__ void prepass_kernel(const float* __restrict__ K, const float* __restrict__ V) {
    size_t i = ((size_t)blockIdx.x * 256 + threadIdx.x) * 4;
    float4 k4 = *(const float4*)(K + i);
    float4 v4 = *(const float4*)(V + i);

    uint32_t kh0 = f2bf(k4.x), kh1 = f2bf(k4.y), kh2 = f2bf(k4.z), kh3 = f2bf(k4.w);
    uint2 khp = make_uint2(kh0 | (kh1 << 16), kh2 | (kh3 << 16));
    uint2 klp = make_uint2(f2bf(k4.x - bf2f(kh0)) | (f2bf(k4.y - bf2f(kh1)) << 16),
                           f2bf(k4.z - bf2f(kh2)) | (f2bf(k4.w - bf2f(kh3)) << 16));
    uint32_t vh0 = f2bf(v4.x), vh1 = f2bf(v4.y), vh2 = f2bf(v4.z), vh3 = f2bf(v4.w);
    uint2 vhp = make_uint2(vh0 | (vh1 << 16), vh2 | (vh3 << 16));
    uint2 vlp = make_uint2(f2bf(v4.x - bf2f(vh0)) | (f2bf(v4.y - bf2f(vh1)) << 16),
                           f2bf(v4.z - bf2f(vh2)) | (f2bf(v4.w - bf2f(vh3)) << 16));

    ((uint2*)g_kh)[i >> 2] = khp;
    ((uint2*)g_kl)[i >> 2] = klp;
    ((uint2*)g_vh)[i >> 2] = vhp;
    ((uint2*)g_vl)[i >> 2] = vlp;
}

// ---------------- main kernel ----------------
static constexpr int STG = 32768;
static constexpr int OKH = 0, OKL = 8192, OVH = 16384, OVL = 24576;
static constexpr int SMEM_BYTES = 2 * STG;
// scale = D^-1/2 * log2(e): exp(s) == exp2(s * log2e) with log2e folded into Q
#define QSCALE 0.1803368801111204f

__device__ __forceinline__ void load_tile(uint32_t st, int h, int ts, int tid) {
#pragma unroll
    for (int c = 0; c < 4; c++) {
        int chunk = tid + 128 * c;
        int row = chunk >> 3;
        int col = (chunk & 7) * 16;
        int g = ts + row;
        bool ok = (unsigned)g < (unsigned)SEQ;
        int sz = ok ? 16 : 0;
        int gc = ok ? g : 0;
        size_t off = (((size_t)h * SEQ + gc) * DD) * 2 + col;
        uint32_t d = st + SWZ(row * 128 + col);
        cpasync16(d + OKH, (const char*)g_kh + off, sz);
        cpasync16(d + OKL, (const char*)g_kl + off, sz);
        cpasync16(d + OVH, (const char*)g_vh + off, sz);
        cpasync16(d + OVL, (const char*)g_vl + off, sz);
    }
}

__global__ __launch_bounds__(128)
void swa_mma_kernel(const float* __restrict__ Q,
                    const int*   __restrict__ wptr,
                    float*       __restrict__ O)
{
    extern __shared__ char smem[];
    const uint32_t sb = smem_u32(smem);
    const int tid = threadIdx.x;
    const int wid = tid >> 5, lane = tid & 31;
    const int gid = lane >> 2, tig = lane & 3;
    const int h  = blockIdx.y;
    const int qs = blockIdx.x * BQ;
    const int w  = *wptr;

    // ---- Q fragments (scaled, split) ----
    uint32_t qh[4][4], ql[4][4];
    {
        const float* qb = Q + ((size_t)h * SEQ + qs) * DD;
        int m0 = wid * 16 + gid;
#pragma unroll
        for (int ks = 0; ks < 4; ks++) {
            int c = ks * 16 + 2 * tig;
#pragma unroll
            for (int half = 0; half < 2; half++)
#pragma unroll
                for (int rh = 0; rh < 2; rh++) {
                    const float* p = qb + (m0 + rh * 8) * DD + c + half * 8;
                    float x0 = p[0] * QSCALE, x1 = p[1] * QSCALE;
                    uint32_t H = cvt2(x1, x0);
                    float e0 = x0 - __uint_as_float(H << 16);
                    float e1 = x1 - __uint_as_float(H & 0xffff0000u);
                    int idx = half * 2 + rh;
                    qh[ks][idx] = H;
                    ql[ks][idx] = cvt2(e1, e0);
                }
        }
    }

    float o[8][4];
#pragma unroll
    for (int j = 0; j < 8; j++)
#pragma unroll
        for (int k = 0; k < 4; k++) o[j][k] = 0.f;
    float l0 = 0.f, l1 = 0.f;

    const int r0 = qs + wid * 16 + gid, r1 = r0 + 8;
    int lo0 = r0 - w; if (lo0 < 0) lo0 = 0;
    int hi0 = r0 + w; if (hi0 > SEQ - 1) hi0 = SEQ - 1;
    int lo1 = r1 - w; if (lo1 < 0) lo1 = 0;
    int hi1 = r1 + w; if (hi1 > SEQ - 1) hi1 = SEQ - 1;

    // per-warp valid key range (for edge-tile 16-key-granule skipping)
    const int Rw = qs + wid * 16;
    int Rlo = Rw - w;      if (Rlo < 0) Rlo = 0;
    int Rhi = Rw + 15 + w; if (Rhi > SEQ - 1) Rhi = SEQ - 1;

    const int T = (BQ + 2 * w + BK - 1) / BK;
    int i0 = 0; while (qs - w + i0 * BK + BK <= 0) i0++;
    int i1 = T - 1; while (qs - w + i1 * BK >= SEQ) i1--;

    load_tile(sb, h, qs - w + i0 * BK, tid);
    CP_COMMIT();

    const int mi = lane >> 3, rr = lane & 7;
    const int keyo = ((mi >> 1) & 1) * 8 + rr;
    const int dbq  = (mi & 1) * 16;
    const int keyq = (mi & 1) * 8 + rr;
    const int db2  = ((mi >> 1) & 1) * 16;

    for (int i = i0; i <= i1; i++) {
        int ts = qs - w + i * BK;
        uint32_t st = sb + ((i - i0) & 1) * STG;
        CP_WAIT0();
        __syncthreads();
        if (i < i1) { load_tile(sb + ((i - i0 + 1) & 1) * STG, h, ts + BK, tid); CP_COMMIT(); }

        int jjlo = (Rlo - ts) >> 4; if (jjlo < 0) jjlo = 0;
        int jjhi = (Rhi - ts) >> 4; if (jjhi > 3) jjhi = 3;

        // ---- S = Qh*Kh + Ql*Kh + Qh*Kl ----
        float s[8][4];
#pragma unroll
        for (int j = 0; j < 8; j++)
#pragma unroll
            for (int k = 0; k < 4; k++) s[j][k] = 0.f;

#pragma unroll
        for (int ks = 0; ks < 4; ks++) {
            int db = 32 * ks + dbq;
#pragma unroll
            for (int jj = 0; jj < 4; jj++) {
                if (jj < jjlo || jj > jjhi) continue;
                uint32_t a = st + OKH + SWZ((16 * jj + keyo) * 128 + db);
                uint32_t kh0[2], kh1[2], kl0[2], kl1[2];
                ldsm4(kh0[0], kh0[1], kh1[0], kh1[1], a);
                ldsm4(kl0[0], kl0[1], kl1[0], kl1[1], a + OKL);
                mma16816(s[2*jj],   qh[ks], kh0);
                mma16816(s[2*jj+1], qh[ks], kh1);
                mma16816(s[2*jj],   ql[ks], kh0);
                mma16816(s[2*jj+1], ql[ks], kh1);
                mma16816(s[2*jj],   qh[ks], kl0);
                mma16816(s[2*jj+1], qh[ks], kl1);
            }
        }

        // ---- mask + exp2 + split P ----
        uint32_t pah[8][2], pal[8][2];
#pragma unroll
        for (int j = 0; j < 8; j++) {
            int c0 = ts + 8 * j + 2 * tig, c1 = c0 + 1;
            float p00 = (c0 >= lo0 && c0 <= hi0) ? ex2f(s[j][0]) : 0.f;
            float p01 = (c1 >= lo0 && c1 <= hi0) ? ex2f(s[j][1]) : 0.f;
            float p10 = (c0 >= lo1 && c0 <= hi1) ? ex2f(s[j][2]) : 0.f;
            float p11 = (c1 >= lo1 && c1 <= hi1) ? ex2f(s[j][3]) : 0.f;
            l0 += p00 + p01; l1 += p10 + p11;
            uint32_t H0 = cvt2(p01, p00);
            uint32_t H1 = cvt2(p11, p10);
            float e00 = p00 - __uint_as_float(H0 << 16);
            float e01 = p01 - __uint_as_float(H0 & 0xffff0000u);
            float e10 = p10 - __uint_as_float(H1 << 16);
            float e11 = p11 - __uint_as_float(H1 & 0xffff0000u);
            pah[j][0] = H0; pah[j][1] = H1;
            pal[j][0] = cvt2(e01, e00);
            pal[j][1] = cvt2(e11, e10);
        }

        // ---- O += Ph*Vh + Pl*Vh + Ph*Vl ----
#pragma unroll
        for (int ks = 0; ks < 4; ks++) {
            if (ks < jjlo || ks > jjhi) continue;
            int keyr = 16 * ks + keyq;
            uint32_t Ah[4] = {pah[2*ks][0], pah[2*ks][1], pah[2*ks+1][0], pah[2*ks+1][1]};
            uint32_t Al[4] = {pal[2*ks][0], pal[2*ks][1], pal[2*ks+1][0], pal[2*ks+1][1]};
#pragma unroll
            for (int jj = 0; jj < 4; jj++) {
                uint32_t a = st + OVH + SWZ(keyr * 128 + 32 * jj + db2);
                uint32_t vh0[2], vh1[2], vl0[2], vl1[2];
                ldsm4t(vh0[0], vh0[1], vh1[0], vh1[1], a);
                ldsm4t(vl0[0], vl0[1], vl1[0], vl1[1], a + (OVL - OVH));
                mma16816(o[2*jj],   Ah, vh0);
                mma16816(o[2*jj+1], Ah, vh1);
                mma16816(o[2*jj],   Al, vh0);
                mma16816(o[2*jj+1], Al, vh1);
                mma16816(o[2*jj],   Ah, vl0);
                mma16816(o[2*jj+1], Ah, vl1);
            }
        }
    }

    // ---- epilogue ----
    l0 += __shfl_xor_sync(0xffffffffu, l0, 1);
    l0 += __shfl_xor_sync(0xffffffffu, l0, 2);
    l1 += __shfl_xor_sync(0xffffffffu, l1, 1);
    l1 += __shfl_xor_sync(0xffffffffu, l1, 2);
    float inv0 = 1.0f / l0, inv1 = 1.0f / l1;

    float* ob0 = O + ((size_t)h * SEQ + r0) * DD;
    float* ob1 = O + ((size_t)h * SEQ + r1) * DD;
#pragma unroll
    for (int j = 0; j < 8; j++) {
        *(float2*)(ob0 + 8 * j + 2 * tig) = make_float2(o[j][0] * inv0, o[j][1] * inv0);
        *(float2*)(ob1 + 8 * j + 2 * tig) = make_float2(o[j][2] * inv1, o[j][3] * inv1);
    }
}

extern "C" void kernel_launch(void* const* d_in, const int* in_sizes, int n_in,
                              void* d_out, int out_size)
{
    const float* q = (const float*)d_in[0];
    const float* k = (const float*)d_in[1];
    const float* v = (const float*)d_in[2];
    const int* wsz = (const int*)d_in[4];
    float* out = (float*)d_out;

    prepass_kernel<<<(int)(KVN / 1024), 256>>>(k, v);

    cudaFuncSetAttribute(swa_mma_kernel,
                         cudaFuncAttributeMaxDynamicSharedMemorySize, SMEM_BYTES);
    dim3 grid(SEQ / BQ, HH);   // (128, 16)
    swa_mma_kernel<<<grid, 128, SMEM_BYTES>>>(q, wsz, out);
}